// round 1
// baseline (speedup 1.0000x reference)
#include <cuda_runtime.h>
#include <math.h>

#define BB 32
#define GG 36
#define AA 5
#define TT 32
#define NCELL (BB*GG*GG*AA)   /* 207360 */
#define IMGSZ 288.0f

// acc layout: 0=conf2_all, 1=conf2_obj, 2=conf1_obj, 3=loc_sum, 4=nme_sum, 5=obj_count
__device__ int    d_winner[NCELL];
__device__ double d_acc[6];

__global__ void init_kernel() {
    int i = blockIdx.x * blockDim.x + threadIdx.x;
    int stride = gridDim.x * blockDim.x;
    for (; i < NCELL; i += stride) d_winner[i] = -1;
    if (blockIdx.x == 0 && threadIdx.x < 6) d_acc[threadIdx.x] = 0.0;
}

__global__ void targets_kernel(const float* __restrict__ bt) {
    int i = blockIdx.x * blockDim.x + threadIdx.x;   // i = b*TT + t (flatten order)
    if (i >= BB * TT) return;
    const float* r = bt + (size_t)i * 5;
    float x = r[0], y = r[1], w = r[2], h = r[3], c4 = r[4];
    bool valid = (x + y + w + h + c4) != 0.0f;
    int gi = (int)(x * (float)GG);
    int gj = (int)(y * (float)GG);
    if (!valid || gi < 0 || gi >= GG || gj < 0 || gj >= GG) return;

    // ground-truth corners in pixels
    float gx1 = (x - w * 0.5f) * IMGSZ;
    float gx2 = (x + w * 0.5f) * IMGSZ;
    float gy1 = (y - h * 0.5f) * IMGSZ;
    float gy2 = (y + h * 0.5f) * IMGSZ;
    float area_g = (gx2 - gx1 + 1.0f) * (gy2 - gy1 + 1.0f);

    float acx = (0.5f + (float)gi) / (float)GG;
    float acy = (0.5f + (float)gj) / (float)GG;

    const float aw[AA] = {0.24f, 0.12f, 0.08f, 0.28f, 0.15f};
    const float ah[AA] = {0.24f, 0.12f, 0.08f, 0.28f, 0.15f};

    int best = 0;
    float best_iou = -1e30f;
#pragma unroll
    for (int a = 0; a < AA; a++) {
        float ax1 = (acx - aw[a] * 0.5f) * IMGSZ;
        float ax2 = (acx + aw[a] * 0.5f) * IMGSZ;
        float ay1 = (acy - ah[a] * 0.5f) * IMGSZ;
        float ay2 = (acy + ah[a] * 0.5f) * IMGSZ;
        float ix1 = fmaxf(gx1, ax1);
        float iy1 = fmaxf(gy1, ay1);
        float ix2 = fminf(gx2, ax2);
        float iy2 = fminf(gy2, ay2);
        float inter  = (ix2 - ix1 + 1.0f) * (iy2 - iy1 + 1.0f);
        float area_a = (ax2 - ax1 + 1.0f) * (ay2 - ay1 + 1.0f);
        float iou = inter / (area_g + area_a - inter + 1e-16f);
        if (iou > best_iou) { best_iou = iou; best = a; }  // strict > == argmax first-max
    }

    int b = i / TT;
    int t = i % TT;
    int cell = ((b * GG + gj) * GG + gi) * AA + best;
    // XLA scatter-set: last update (largest t within this b) wins
    atomicMax(&d_winner[cell], t);
}

__device__ __forceinline__ float smooth_l1(float d) {
    float ad = fabsf(d);
    return (ad < 1.0f) ? 0.5f * d * d : ad - 0.5f;
}

__global__ void reduce_kernel(const float* __restrict__ bp,
                              const float* __restrict__ lmp,
                              const float* __restrict__ bt,
                              const float* __restrict__ lmt) {
    int c = blockIdx.x * blockDim.x + threadIdx.x;
    double v0 = 0.0, v1 = 0.0, v2 = 0.0, v3 = 0.0, v4 = 0.0, v5 = 0.0;

    if (c < NCELL) {
        float conf = bp[(size_t)c * 5 + 4];
        v0 = (double)conf * (double)conf;
        int t = d_winner[c];
        if (t >= 0) {
            v5 = 1.0;
            v1 = v0;
            float cm1 = conf - 1.0f;
            v2 = (double)cm1 * (double)cm1;

            int b = c / (GG * GG * AA);
            const float* r = bt + (size_t)(b * TT + t) * 5;
            float l0 = log1pf(r[0]);
            float l1 = log1pf(r[1]);
            float l2 = log1pf(r[2]);
            float l3 = log1pf(r[3]);

            float loc = 0.0f;
            loc += smooth_l1(bp[(size_t)c * 5 + 0] - l0);
            loc += smooth_l1(bp[(size_t)c * 5 + 1] - l1);
            loc += smooth_l1(bp[(size_t)c * 5 + 2] - l2);
            loc += smooth_l1(bp[(size_t)c * 5 + 3] - l3);
            v3 = (double)loc;

            float nf = sqrtf(l2 * l3);
            const float2* lt = (const float2*)(lmt + (size_t)(b * TT + t) * 136);
            const float2* lp = (const float2*)(lmp + (size_t)c * 136);
            float s = 0.0f;
#pragma unroll 4
            for (int k = 0; k < 68; k++) {
                float2 a = lt[k];
                float2 p = lp[k];
                float dx = a.x - p.x;
                float dy = a.y - p.y;
                s += sqrtf(dx * dx + dy * dy);
            }
            v4 = (double)(s / nf);
        }
    }

    // block reduction of 6 doubles
    double vals[6] = {v0, v1, v2, v3, v4, v5};
    __shared__ double sh[6][8];
    int lane = threadIdx.x & 31;
    int wid  = threadIdx.x >> 5;
#pragma unroll
    for (int j = 0; j < 6; j++) {
        double x = vals[j];
        for (int o = 16; o > 0; o >>= 1)
            x += __shfl_down_sync(0xffffffffu, x, o);
        if (lane == 0) sh[j][wid] = x;
    }
    __syncthreads();
    if (wid == 0) {
#pragma unroll
        for (int j = 0; j < 6; j++) {
            double x = (lane < 8) ? sh[j][lane] : 0.0;
            for (int o = 4; o > 0; o >>= 1)
                x += __shfl_down_sync(0xffffffffu, x, o);
            if (lane == 0 && x != 0.0) atomicAdd(&d_acc[j], x);
        }
    }
}

__global__ void finalize_kernel(float* __restrict__ out) {
    double conf2_all = d_acc[0];
    double conf2_obj = d_acc[1];
    double conf1_obj = d_acc[2];
    double loc_sum   = d_acc[3];
    double nme_sum   = d_acc[4];
    double cnt       = d_acc[5];

    double n_obj   = fmax(cnt, 1.0);
    double n_noobj = fmax((double)NCELL - cnt, 1.0);

    double nme  = 2.0 * nme_sum / (68.0 * n_obj);
    double loc  = 5.0 * loc_sum / (n_obj * 4.0);
    double conf = 0.5 * (conf2_all - conf2_obj) / n_noobj + conf1_obj / n_obj;

    out[0] = (float)nme;
    out[1] = (float)loc;
    out[2] = (float)conf;
}

extern "C" void kernel_launch(void* const* d_in, const int* in_sizes, int n_in,
                              void* d_out, int out_size) {
    const float* bbox_pred = (const float*)d_in[0];   // (32,36,36,5,5)
    const float* lm_pred   = (const float*)d_in[1];   // (32,36,36,5,68,2)
    const float* bbox_tgt  = (const float*)d_in[2];   // (32,32,5)
    const float* lm_tgt    = (const float*)d_in[3];   // (32,32,68,2)
    float* out = (float*)d_out;

    init_kernel<<<256, 256>>>();
    targets_kernel<<<(BB * TT + 127) / 128, 128>>>(bbox_tgt);
    reduce_kernel<<<(NCELL + 255) / 256, 256>>>(bbox_pred, lm_pred, bbox_tgt, lm_tgt);
    finalize_kernel<<<1, 1>>>(out);
}

// round 2
// speedup vs baseline: 1.4728x; 1.4728x over previous
#include <cuda_runtime.h>
#include <math.h>

#define BB 32
#define GG 36
#define AA 5
#define TT 32
#define NCELL (BB*GG*GG*AA)       /* 207360 */
#define NFLOAT (NCELL*5)          /* 1036800 */
#define NVEC (NFLOAT/4)           /* 259200  */
#define IMGSZ 288.0f

// acc: 0=conf2_all, 1=conf2_obj, 2=conf1_obj, 3=loc_sum, 4=nme_sum
__device__ double d_acc[5];
__device__ int    d_count;
__device__ int    d_done;
__device__ int    d_obj_cell[BB*TT];
__device__ int    d_obj_bt[BB*TT];

// ---------------------------------------------------------------------------
// K1: one block, 1024 threads. Build compact obj list with last-t-wins dedupe.
// ---------------------------------------------------------------------------
__global__ void setup_kernel(const float* __restrict__ bt) {
    __shared__ int cells[BB*TT];
    int i = threadIdx.x;               // i = b*TT + t  (flatten order)

    if (i < 5) d_acc[i] = 0.0;
    if (i == 0) { d_count = 0; d_done = 0; }

    const float* r = bt + (size_t)i * 5;
    float x = r[0], y = r[1], w = r[2], h = r[3], c4 = r[4];
    bool valid = (x + y + w + h + c4) != 0.0f;
    int gi = (int)(x * (float)GG);
    int gj = (int)(y * (float)GG);

    int cell = -1;
    if (valid && gi >= 0 && gi < GG && gj >= 0 && gj < GG) {
        float gx1 = (x - w * 0.5f) * IMGSZ;
        float gx2 = (x + w * 0.5f) * IMGSZ;
        float gy1 = (y - h * 0.5f) * IMGSZ;
        float gy2 = (y + h * 0.5f) * IMGSZ;
        float area_g = (gx2 - gx1 + 1.0f) * (gy2 - gy1 + 1.0f);

        float acx = (0.5f + (float)gi) / (float)GG;
        float acy = (0.5f + (float)gj) / (float)GG;

        const float aw[AA] = {0.24f, 0.12f, 0.08f, 0.28f, 0.15f};

        int best = 0;
        float best_iou = -1e30f;
#pragma unroll
        for (int a = 0; a < AA; a++) {
            float ax1 = (acx - aw[a] * 0.5f) * IMGSZ;
            float ax2 = (acx + aw[a] * 0.5f) * IMGSZ;
            float ay1 = (acy - aw[a] * 0.5f) * IMGSZ;
            float ay2 = (acy + aw[a] * 0.5f) * IMGSZ;
            float ix1 = fmaxf(gx1, ax1);
            float iy1 = fmaxf(gy1, ay1);
            float ix2 = fminf(gx2, ax2);
            float iy2 = fminf(gy2, ay2);
            float inter  = (ix2 - ix1 + 1.0f) * (iy2 - iy1 + 1.0f);
            float area_a = (ax2 - ax1 + 1.0f) * (ay2 - ay1 + 1.0f);
            float iou = inter / (area_g + area_a - inter + 1e-16f);
            if (iou > best_iou) { best_iou = iou; best = a; }  // first-max argmax
        }
        int b = i / TT;
        cell = ((b * GG + gj) * GG + gi) * AA + best;
    }
    cells[i] = cell;
    __syncthreads();

    // keep only if no later t within same b hits same cell (last writer wins)
    if (cell >= 0) {
        int b = i / TT, t = i % TT;
        bool win = true;
        for (int tp = t + 1; tp < TT; tp++)
            if (cells[b * TT + tp] == cell) { win = false; break; }
        if (win) {
            int idx = atomicAdd(&d_count, 1);
            d_obj_cell[idx] = cell;
            d_obj_bt[idx]   = i;
        }
    }
}

__device__ __forceinline__ float smooth_l1(float d) {
    float ad = fabsf(d);
    return (ad < 1.0f) ? 0.5f * d * d : ad - 0.5f;
}

// ---------------------------------------------------------------------------
// K2: streaming conf pass + per-warp obj losses + last-block finalize.
// ---------------------------------------------------------------------------
__global__ void main_kernel(const float* __restrict__ bp,
                            const float* __restrict__ lmp,
                            const float* __restrict__ bt,
                            const float* __restrict__ lmt,
                            float* __restrict__ out) {
    int tid   = blockIdx.x * blockDim.x + threadIdx.x;
    int nthr  = gridDim.x * blockDim.x;
    int lane  = threadIdx.x & 31;
    int wid   = threadIdx.x >> 5;
    int gwarp = tid >> 5;
    int nwarp = nthr >> 5;

    double v0 = 0.0, v1 = 0.0, v2 = 0.0, v3 = 0.0, v4 = 0.0;

    // --- conf^2 over all cells, fully coalesced float4 stream ---
    const float4* bp4 = (const float4*)bp;
    for (int i = tid; i < NVEC; i += nthr) {
        float4 v = bp4[i];
        int rem = (4 * i) % 5;          // conf index == 4 (mod 5)
        if (rem != 0) {
            float vv[4] = {v.x, v.y, v.z, v.w};
            float c = vv[4 - rem];
            v0 += (double)c * (double)c;
        }
    }

    // --- obj items: one warp per item ---
    int count = d_count;
    for (int item = gwarp; item < count; item += nwarp) {
        int cell = d_obj_cell[item];
        int btid = d_obj_bt[item];

        const float2* lt = (const float2*)(lmt + (size_t)btid * 136);
        const float2* lp = (const float2*)(lmp + (size_t)cell * 136);
        float s = 0.0f;
        for (int k = lane; k < 68; k += 32) {
            float2 a = lt[k];
            float2 p = lp[k];
            float dx = a.x - p.x;
            float dy = a.y - p.y;
            s += sqrtf(dx * dx + dy * dy);
        }
#pragma unroll
        for (int o = 16; o > 0; o >>= 1)
            s += __shfl_down_sync(0xffffffffu, s, o);

        if (lane == 0) {
            const float* r = bt + (size_t)btid * 5;
            float l0 = log1pf(r[0]);
            float l1 = log1pf(r[1]);
            float l2 = log1pf(r[2]);
            float l3 = log1pf(r[3]);

            const float* p = bp + (size_t)cell * 5;
            float loc = smooth_l1(p[0] - l0) + smooth_l1(p[1] - l1)
                      + smooth_l1(p[2] - l2) + smooth_l1(p[3] - l3);
            v3 += (double)loc;

            float conf = p[4];
            v1 += (double)conf * (double)conf;
            float cm1 = conf - 1.0f;
            v2 += (double)cm1 * (double)cm1;

            float nf = sqrtf(l2 * l3);
            v4 += (double)(s / nf);
        }
    }

    // --- block reduction of 5 doubles ---
    double vals[5] = {v0, v1, v2, v3, v4};
    __shared__ double sh[5][8];
#pragma unroll
    for (int j = 0; j < 5; j++) {
        double x = vals[j];
        for (int o = 16; o > 0; o >>= 1)
            x += __shfl_down_sync(0xffffffffu, x, o);
        if (lane == 0) sh[j][wid] = x;
    }
    __syncthreads();
    if (threadIdx.x == 0) {
#pragma unroll
        for (int j = 0; j < 5; j++) {
            double x = sh[j][0];
            for (int k = 1; k < 8; k++) x += sh[j][k];
            if (x != 0.0) atomicAdd(&d_acc[j], x);
        }
        __threadfence();
        int ticket = atomicAdd(&d_done, 1);
        if (ticket == gridDim.x - 1) {
            // all other blocks' d_acc updates are visible (atomic + fence order)
            double conf2_all = atomicAdd(&d_acc[0], 0.0);
            double conf2_obj = atomicAdd(&d_acc[1], 0.0);
            double conf1_obj = atomicAdd(&d_acc[2], 0.0);
            double loc_sum   = atomicAdd(&d_acc[3], 0.0);
            double nme_sum   = atomicAdd(&d_acc[4], 0.0);
            double cnt       = (double)count;

            double n_obj   = fmax(cnt, 1.0);
            double n_noobj = fmax((double)NCELL - cnt, 1.0);

            out[0] = (float)(2.0 * nme_sum / (68.0 * n_obj));
            out[1] = (float)(5.0 * loc_sum / (n_obj * 4.0));
            out[2] = (float)(0.5 * (conf2_all - conf2_obj) / n_noobj
                             + conf1_obj / n_obj);
        }
    }
}

extern "C" void kernel_launch(void* const* d_in, const int* in_sizes, int n_in,
                              void* d_out, int out_size) {
    const float* bbox_pred = (const float*)d_in[0];   // (32,36,36,5,5)
    const float* lm_pred   = (const float*)d_in[1];   // (32,36,36,5,68,2)
    const float* bbox_tgt  = (const float*)d_in[2];   // (32,32,5)
    const float* lm_tgt    = (const float*)d_in[3];   // (32,32,68,2)
    float* out = (float*)d_out;

    setup_kernel<<<1, BB * TT>>>(bbox_tgt);
    main_kernel<<<296, 256>>>(bbox_pred, lm_pred, bbox_tgt, lm_tgt, out);
}